// round 6
// baseline (speedup 1.0000x reference)
#include <cuda_runtime.h>
#include <math.h>

// Input order (metadata): 0:N 1:Zf 2:rij 3:cutoff_values 4:idx_i 5:idx_j
//                         6:adiv 7:apow 8:c1 9:c2 10:c3 11:c4 12:a1 13:a2 14:a3 15:a4
// Output: float[N]

#define KEHALF 7.199822675975274f
#define MAX_ATOMS 500000

struct ZParams {
    float sp_adiv, sp_apow;
    float c1n, c2n, c3n, c4n;
    float s1, s2, s3, s4;
};

__device__ ZParams g_p;
__device__ unsigned char g_z8[MAX_ATOMS];   // compact species table (1..94)

static __device__ __forceinline__ float sp_d(float x) {
    return (float)log1p(exp((double)x));    // one-time scalar prep, exact
}

__global__ void zbl_prep_kernel(const float* __restrict__ adiv,
                                const float* __restrict__ apow,
                                const float* __restrict__ c1,
                                const float* __restrict__ c2,
                                const float* __restrict__ c3,
                                const float* __restrict__ c4,
                                const float* __restrict__ a1,
                                const float* __restrict__ a2,
                                const float* __restrict__ a3,
                                const float* __restrict__ a4) {
    if (threadIdx.x == 0 && blockIdx.x == 0) {
        float c1p = sp_d(c1[0]);
        float c2p = sp_d(c2[0]);
        float c3p = sp_d(c3[0]);
        float c4p = sp_d(c4[0]);
        float inv = 1.0f / (c1p + c2p + c3p + c4p);
        ZParams p;
        p.sp_adiv = sp_d(adiv[0]);
        p.sp_apow = sp_d(apow[0]);
        p.c1n = c1p * inv;
        p.c2n = c2p * inv;
        p.c3n = c3p * inv;
        p.c4n = c4p * inv;
        p.s1 = sp_d(a1[0]);
        p.s2 = sp_d(a2[0]);
        p.s3 = sp_d(a3[0]);
        p.s4 = sp_d(a4[0]);
        g_p = p;
    }
}

// Compress Zf (float ints 1..94) into uint8 table: 2MB -> 500KB gather footprint.
__global__ void zbl_pack_kernel(const float* __restrict__ Zf, int n) {
    int t = blockIdx.x * blockDim.x + threadIdx.x;
    if (t < n) g_z8[t] = (unsigned char)(Zf[t] + 0.5f);
}

__device__ __forceinline__ float zbl_pair(const ZParams& p,
                                          float Zi, float Zj,
                                          float r, float cut) {
    // z = Z^sp(apow)  -> MUFU.LG2 + FMUL + MUFU.EX2
    float zi = __powf(Zi, p.sp_apow);
    float zj = __powf(Zj, p.sp_apow);
    float a  = (zi + zj) * p.sp_adiv;
    float ar = a * r;
    float f = p.c1n * __expf(-p.s1 * ar)
            + p.c2n * __expf(-p.s2 * ar)
            + p.c3n * __expf(-p.s3 * ar)
            + p.c4n * __expf(-p.s4 * ar);
    float zizj = Zi * Zj;
    return __fdividef(KEHALF * f * cut * zizj, r);
}

__global__ void __launch_bounds__(256)
zbl_pair_kernel4(const float4* __restrict__ rij4,
                 const float4* __restrict__ cut4,
                 const int4* __restrict__ ii4,
                 const int4* __restrict__ jj4,
                 float* __restrict__ out,
                 int n4) {
    int t = blockIdx.x * blockDim.x + threadIdx.x;
    if (t >= n4) return;

    ZParams p = g_p;

    // Streaming reads: evict-first so they don't pollute L1/L2 for the gathers
    float4 r  = __ldcs(&rij4[t]);
    float4 c  = __ldcs(&cut4[t]);
    int4   ii = __ldcs(&ii4[t]);
    int4   jj = __ldcs(&jj4[t]);

    int ia[4] = {ii.x, ii.y, ii.z, ii.w};
    int ja[4] = {jj.x, jj.y, jj.z, jj.w};
    float rr[4] = {r.x, r.y, r.z, r.w};
    float cc[4] = {c.x, c.y, c.z, c.w};

    // Batch the 8 random byte-gathers first for maximum MLP
    float Zi[4], Zj[4];
#pragma unroll
    for (int k = 0; k < 4; k++) {
        Zi[k] = (float)__ldg(&g_z8[ia[k]]);
        Zj[k] = (float)__ldg(&g_z8[ja[k]]);
    }

    float contrib[4];
#pragma unroll
    for (int k = 0; k < 4; k++) {
        contrib[k] = zbl_pair(p, Zi[k], Zj[k], rr[k], cc[k]);
    }

#pragma unroll
    for (int k = 0; k < 4; k++) {
        atomicAdd(out + ia[k], contrib[k]);
    }
}

__global__ void zbl_pair_tail(const float* __restrict__ rij,
                              const float* __restrict__ cut,
                              const int* __restrict__ idx_i,
                              const int* __restrict__ idx_j,
                              float* __restrict__ out,
                              int start, int n) {
    int t = start + blockIdx.x * blockDim.x + threadIdx.x;
    if (t >= n) return;
    ZParams p = g_p;
    float Zi = (float)g_z8[idx_i[t]];
    float Zj = (float)g_z8[idx_j[t]];
    float contrib = zbl_pair(p, Zi, Zj, rij[t], cut[t]);
    atomicAdd(out + idx_i[t], contrib);
}

extern "C" void kernel_launch(void* const* d_in, const int* in_sizes, int n_in,
                              void* d_out, int out_size) {
    const float* Zf    = (const float*)d_in[1];
    const float* rij   = (const float*)d_in[2];
    const float* cut   = (const float*)d_in[3];
    const int*   idx_i = (const int*)d_in[4];
    const int*   idx_j = (const int*)d_in[5];
    const float* adiv  = (const float*)d_in[6];
    const float* apow  = (const float*)d_in[7];
    const float* c1    = (const float*)d_in[8];
    const float* c2    = (const float*)d_in[9];
    const float* c3    = (const float*)d_in[10];
    const float* c4    = (const float*)d_in[11];
    const float* a1    = (const float*)d_in[12];
    const float* a2    = (const float*)d_in[13];
    const float* a3    = (const float*)d_in[14];
    const float* a4    = (const float*)d_in[15];
    float* out = (float*)d_out;

    int n_atoms = in_sizes[1];
    int n_pairs = in_sizes[2];

    // 1) derived scalar parameters + compact Z table (overlappable, cheap)
    zbl_prep_kernel<<<1, 32>>>(adiv, apow, c1, c2, c3, c4, a1, a2, a3, a4);
    zbl_pack_kernel<<<(n_atoms + 255) / 256, 256>>>(Zf, n_atoms);

    // 2) zero the poisoned output
    cudaMemsetAsync(d_out, 0, (size_t)out_size * sizeof(float), 0);

    // 3) main pair sweep, 4 pairs per thread
    int n4 = n_pairs / 4;
    if (n4 > 0) {
        int threads = 256;
        int blocks = (n4 + threads - 1) / threads;
        zbl_pair_kernel4<<<blocks, threads>>>(
            (const float4*)rij, (const float4*)cut,
            (const int4*)idx_i, (const int4*)idx_j, out, n4);
    }

    // 4) tail (n_pairs not divisible by 4)
    int done = n4 * 4;
    int rem = n_pairs - done;
    if (rem > 0) {
        zbl_pair_tail<<<(rem + 255) / 256, 256>>>(
            rij, cut, idx_i, idx_j, out, done, n_pairs);
    }
}

// round 7
// speedup vs baseline: 1.1028x; 1.1028x over previous
#include <cuda_runtime.h>
#include <math.h>

// Input order (metadata): 0:N 1:Zf 2:rij 3:cutoff_values 4:idx_i 5:idx_j
//                         6:adiv 7:apow 8:c1 9:c2 10:c3 11:c4 12:a1 13:a2 14:a3 15:a4
// Output: float[N]

#define KEHALF 7.199822675975274f

struct ZParams {
    float sp_adiv, sp_apow;
    float c1n, c2n, c3n, c4n;
    float s1, s2, s3, s4;
};

__device__ ZParams g_p;

// Fast float softplus: log1pf(expf(x)); numerically safe for the small scalar range here.
static __device__ __forceinline__ float sp_f(float x) {
    return log1pf(__expf(x));
}

// One warp: lanes 0..9 each softplus one scalar in parallel (short float chains),
// lane 0 assembles the struct via shuffles. ~2us instead of 23us serial-DP.
__global__ void zbl_prep_kernel(const float* __restrict__ adiv,
                                const float* __restrict__ apow,
                                const float* __restrict__ c1,
                                const float* __restrict__ c2,
                                const float* __restrict__ c3,
                                const float* __restrict__ c4,
                                const float* __restrict__ a1,
                                const float* __restrict__ a2,
                                const float* __restrict__ a3,
                                const float* __restrict__ a4) {
    int lane = threadIdx.x;
    const float* srcs[10] = {adiv, apow, c1, c2, c3, c4, a1, a2, a3, a4};
    float v = 0.0f;
    if (lane < 10) v = sp_f(srcs[lane][0]);
    // Broadcast all 10 results to every lane
    float sp_adiv = __shfl_sync(0xffffffffu, v, 0);
    float sp_apow = __shfl_sync(0xffffffffu, v, 1);
    float c1p     = __shfl_sync(0xffffffffu, v, 2);
    float c2p     = __shfl_sync(0xffffffffu, v, 3);
    float c3p     = __shfl_sync(0xffffffffu, v, 4);
    float c4p     = __shfl_sync(0xffffffffu, v, 5);
    float s1      = __shfl_sync(0xffffffffu, v, 6);
    float s2      = __shfl_sync(0xffffffffu, v, 7);
    float s3      = __shfl_sync(0xffffffffu, v, 8);
    float s4      = __shfl_sync(0xffffffffu, v, 9);
    if (lane == 0) {
        float inv = 1.0f / (c1p + c2p + c3p + c4p);
        ZParams p;
        p.sp_adiv = sp_adiv;
        p.sp_apow = sp_apow;
        p.c1n = c1p * inv;
        p.c2n = c2p * inv;
        p.c3n = c3p * inv;
        p.c4n = c4p * inv;
        p.s1 = s1; p.s2 = s2; p.s3 = s3; p.s4 = s4;
        g_p = p;
    }
}

__device__ __forceinline__ float zbl_pair(const ZParams& p,
                                          float Zi, float Zj,
                                          float r, float cut) {
    // z = Z^sp(apow)  -> MUFU.LG2 + FMUL + MUFU.EX2
    float zi = __powf(Zi, p.sp_apow);
    float zj = __powf(Zj, p.sp_apow);
    float a  = (zi + zj) * p.sp_adiv;
    float ar = a * r;
    float f = p.c1n * __expf(-p.s1 * ar)
            + p.c2n * __expf(-p.s2 * ar)
            + p.c3n * __expf(-p.s3 * ar)
            + p.c4n * __expf(-p.s4 * ar);
    float zizj = Zi * Zj;
    return __fdividef(KEHALF * f * cut * zizj, r);
}

__global__ void __launch_bounds__(256)
zbl_pair_kernel4(const float* __restrict__ Zf,
                 const float4* __restrict__ rij4,
                 const float4* __restrict__ cut4,
                 const int4* __restrict__ ii4,
                 const int4* __restrict__ jj4,
                 float* __restrict__ out,
                 int n4) {
    int t = blockIdx.x * blockDim.x + threadIdx.x;
    if (t >= n4) return;

    ZParams p = g_p;

    // Streaming reads: evict-first so they don't pollute L1/L2 for the gathers
    float4 r  = __ldcs(&rij4[t]);
    float4 c  = __ldcs(&cut4[t]);
    int4   ii = __ldcs(&ii4[t]);
    int4   jj = __ldcs(&jj4[t]);

    int ia[4] = {ii.x, ii.y, ii.z, ii.w};
    int ja[4] = {jj.x, jj.y, jj.z, jj.w};
    float rr[4] = {r.x, r.y, r.z, r.w};
    float cc[4] = {c.x, c.y, c.z, c.w};

    // Batch the 8 random gathers first for maximum MLP
    float Zi[4], Zj[4];
#pragma unroll
    for (int k = 0; k < 4; k++) {
        Zi[k] = __ldg(Zf + ia[k]);
        Zj[k] = __ldg(Zf + ja[k]);
    }

    float contrib[4];
#pragma unroll
    for (int k = 0; k < 4; k++) {
        contrib[k] = zbl_pair(p, Zi[k], Zj[k], rr[k], cc[k]);
    }

#pragma unroll
    for (int k = 0; k < 4; k++) {
        atomicAdd(out + ia[k], contrib[k]);
    }
}

__global__ void zbl_pair_tail(const float* __restrict__ Zf,
                              const float* __restrict__ rij,
                              const float* __restrict__ cut,
                              const int* __restrict__ idx_i,
                              const int* __restrict__ idx_j,
                              float* __restrict__ out,
                              int start, int n) {
    int t = start + blockIdx.x * blockDim.x + threadIdx.x;
    if (t >= n) return;
    ZParams p = g_p;
    float contrib = zbl_pair(p, __ldg(Zf + idx_i[t]), __ldg(Zf + idx_j[t]),
                             rij[t], cut[t]);
    atomicAdd(out + idx_i[t], contrib);
}

extern "C" void kernel_launch(void* const* d_in, const int* in_sizes, int n_in,
                              void* d_out, int out_size) {
    const float* Zf    = (const float*)d_in[1];
    const float* rij   = (const float*)d_in[2];
    const float* cut   = (const float*)d_in[3];
    const int*   idx_i = (const int*)d_in[4];
    const int*   idx_j = (const int*)d_in[5];
    const float* adiv  = (const float*)d_in[6];
    const float* apow  = (const float*)d_in[7];
    const float* c1    = (const float*)d_in[8];
    const float* c2    = (const float*)d_in[9];
    const float* c3    = (const float*)d_in[10];
    const float* c4    = (const float*)d_in[11];
    const float* a1    = (const float*)d_in[12];
    const float* a2    = (const float*)d_in[13];
    const float* a3    = (const float*)d_in[14];
    const float* a4    = (const float*)d_in[15];
    float* out = (float*)d_out;

    int n_pairs = in_sizes[2];

    // 1) derived scalar parameters (fast, parallel float softplus)
    zbl_prep_kernel<<<1, 32>>>(adiv, apow, c1, c2, c3, c4, a1, a2, a3, a4);

    // 2) zero the poisoned output
    cudaMemsetAsync(d_out, 0, (size_t)out_size * sizeof(float), 0);

    // 3) main pair sweep, 4 pairs per thread
    int n4 = n_pairs / 4;
    if (n4 > 0) {
        int threads = 256;
        int blocks = (n4 + threads - 1) / threads;
        zbl_pair_kernel4<<<blocks, threads>>>(
            Zf, (const float4*)rij, (const float4*)cut,
            (const int4*)idx_i, (const int4*)idx_j, out, n4);
    }

    // 4) tail (n_pairs not divisible by 4)
    int done = n4 * 4;
    int rem = n_pairs - done;
    if (rem > 0) {
        zbl_pair_tail<<<(rem + 255) / 256, 256>>>(
            Zf, rij, cut, idx_i, idx_j, out, done, n_pairs);
    }
}